// round 1
// baseline (speedup 1.0000x reference)
#include <cuda_runtime.h>

#define CAPS 32
#define FEAT 256

__global__ __launch_bounds__(256, 2)
void router_kernel(const float* __restrict__ x,
                   const float* __restrict__ bias,
                   float* __restrict__ out, int B)
{
    __shared__ float warp_part[8][32];
    __shared__ float attn_s[32];

    const int tid  = threadIdx.x;        // feature column j = tid
    const int lane = tid & 31;
    const int wid  = tid >> 5;

    // bias column j in registers, loaded once per CTA (persistent grid)
    float breg[CAPS];
#pragma unroll
    for (int i = 0; i < CAPS; i++) breg[i] = bias[i * FEAT + tid];

    for (int b = blockIdx.x; b < B; b += gridDim.x) {
        const float* xb = x + (size_t)b * (CAPS * FEAT) + tid;

        // Load column j of this batch row: x[b, i, j], i=0..31 (coalesced, streamed)
        float xv[CAPS];
#pragma unroll
        for (int i = 0; i < CAPS; i++) xv[i] = __ldcs(xb + i * FEAT);

        // t[j] = sum_i x[b,i,j]
        float t = 0.f;
#pragma unroll
        for (int i = 0; i < CAPS; i++) t += xv[i];

        // p[i] = x[b,i,j] * t[j]  (per-thread partial of score[i])
        float p[CAPS];
#pragma unroll
        for (int i = 0; i < CAPS; i++) p[i] = xv[i] * t;

        // Warp transpose-reduce: 31 SHFLs; lane l ends with
        // sum over this warp's 32 features of p[l].
#pragma unroll
        for (int d = 16; d >= 1; d >>= 1) {
            const bool up = (lane & d) != 0;
#pragma unroll
            for (int k = 0; k < d; k++) {
                float send = up ? p[k] : p[k + d];
                float recv = __shfl_xor_sync(0xffffffffu, send, d);
                p[k] = (up ? p[k + d] : p[k]) + recv;
            }
        }
        warp_part[wid][lane] = p[0];
        __syncthreads();

        // Warp 0: combine 8 warp partials, softmax over 32 capsules
        if (wid == 0) {
            float s = 0.f;
#pragma unroll
            for (int w = 0; w < 8; w++) s += warp_part[w][lane];
            s *= (1.0f / 16.0f);            // 1/sqrt(FEAT)

            float m = s;
#pragma unroll
            for (int d = 16; d >= 1; d >>= 1)
                m = fmaxf(m, __shfl_xor_sync(0xffffffffu, m, d));
            float e = __expf(s - m);
            float sum = e;
#pragma unroll
            for (int d = 16; d >= 1; d >>= 1)
                sum += __shfl_xor_sync(0xffffffffu, sum, d);
            attn_s[lane] = e / sum;
        }
        __syncthreads();

        // out[b,j] = sum_i x[b,i,j] * (attn[b,i] + bias[i,j])
        float acc = 0.f;
#pragma unroll
        for (int i = 0; i < CAPS; i++)
            acc += xv[i] * (attn_s[i] + breg[i]);
        out[(size_t)b * FEAT + tid] = acc;
    }
}

extern "C" void kernel_launch(void* const* d_in, const int* in_sizes, int n_in,
                              void* d_out, int out_size)
{
    const float* x    = (const float*)d_in[0];   // inputs [B, 32, 256] fp32
    const float* bias = (const float*)d_in[1];   // bias   [32, 256]   fp32
    float* out        = (float*)d_out;           // out    [B, 256]    fp32

    const int B = in_sizes[0] / (CAPS * FEAT);
    // Persistent grid: ~2 CTAs per SM (152 SMs on GB300), grid-stride over b.
    int grid = 304;
    if (grid > B) grid = B;
    router_kernel<<<grid, 256>>>(x, bias, out, B);
}

// round 2
// speedup vs baseline: 1.1605x; 1.1605x over previous
#include <cuda_runtime.h>
#include <cstdint>

#define CAPS 32
#define FEAT 256
#define ROW_BYTES (CAPS * FEAT * 4)        // 32768
#define SMEM_BYTES (2 * ROW_BYTES + 16)    // 2 row buffers + 2 mbarriers

extern __shared__ unsigned char smem_raw[];

__device__ __forceinline__ uint32_t smem_u32(const void* p) {
    uint32_t a;
    asm("{ .reg .u64 t; cvta.to.shared.u64 t, %1; cvt.u32.u64 %0, t; }"
        : "=r"(a) : "l"(p));
    return a;
}

__device__ __forceinline__ void mbar_init(uint32_t addr, uint32_t count) {
    asm volatile("mbarrier.init.shared::cta.b64 [%0], %1;"
                 :: "r"(addr), "r"(count) : "memory");
}

__device__ __forceinline__ void mbar_expect_tx(uint32_t addr, uint32_t bytes) {
    asm volatile("mbarrier.arrive.expect_tx.shared::cta.b64 _, [%0], %1;"
                 :: "r"(addr), "r"(bytes) : "memory");
}

__device__ __forceinline__ void bulk_copy_g2s(uint32_t dst, const void* src,
                                              uint32_t bytes, uint32_t mbar) {
    asm volatile(
        "cp.async.bulk.shared::cta.global.mbarrier::complete_tx::bytes "
        "[%0], [%1], %2, [%3];"
        :: "r"(dst), "l"(src), "r"(bytes), "r"(mbar) : "memory");
}

__device__ __forceinline__ void mbar_wait(uint32_t addr, uint32_t parity) {
    asm volatile(
        "{\n\t"
        ".reg .pred P;\n"
        "WAIT_%=:\n\t"
        "mbarrier.try_wait.parity.acquire.cta.shared::cta.b64 P, [%0], %1, 10000000;\n\t"
        "@!P bra WAIT_%=;\n\t"
        "}"
        :: "r"(addr), "r"(parity) : "memory");
}

__global__ __launch_bounds__(256, 2)
void router_kernel(const float* __restrict__ x,
                   const float* __restrict__ bias,
                   float* __restrict__ out, int B)
{
    __shared__ float warp_part[8][32];

    float* buf[2] = { (float*)smem_raw, (float*)(smem_raw + ROW_BYTES) };
    const uint32_t mbar[2] = { smem_u32(smem_raw + 2 * ROW_BYTES),
                               smem_u32(smem_raw + 2 * ROW_BYTES + 8) };

    const int tid  = threadIdx.x;       // feature column j = tid
    const int lane = tid & 31;
    const int wid  = tid >> 5;
    const int grid = gridDim.x;

    if (tid == 0) {
        mbar_init(mbar[0], 1);
        mbar_init(mbar[1], 1);
    }
    __syncthreads();

    // bias column j in registers, loaded once per CTA (persistent grid)
    float breg[CAPS];
#pragma unroll
    for (int i = 0; i < CAPS; i++) breg[i] = bias[i * FEAT + tid];

    // Prologue: prefetch first row into buf0
    if (blockIdx.x < B && tid == 0) {
        mbar_expect_tx(mbar[0], ROW_BYTES);
        bulk_copy_g2s(smem_u32(buf[0]),
                      x + (size_t)blockIdx.x * (CAPS * FEAT),
                      ROW_BYTES, mbar[0]);
    }

    uint32_t phase[2] = { 0, 0 };
    int cur = 0;

    for (int b = blockIdx.x; b < B; b += grid, cur ^= 1) {
        // Wait for current row's DMA
        mbar_wait(mbar[cur], phase[cur]);
        phase[cur] ^= 1;

        // Issue prefetch of the next row into the other buffer.
        // Safe: all threads' reads of buf[cur^1] (iteration k-1) precede that
        // iteration's __syncthreads, which thread 0 has passed to get here.
        const int nb = b + grid;
        if (nb < B && tid == 0) {
            mbar_expect_tx(mbar[cur ^ 1], ROW_BYTES);
            bulk_copy_g2s(smem_u32(buf[cur ^ 1]),
                          x + (size_t)nb * (CAPS * FEAT),
                          ROW_BYTES, mbar[cur ^ 1]);
        }

        // Read column j of the row from smem: x[b, i, j], i = 0..31
        const float* bp = buf[cur] + tid;
        float xv[CAPS];
#pragma unroll
        for (int i = 0; i < CAPS; i++) xv[i] = bp[i * FEAT];

        // t[j] = sum_i x[b,i,j]
        float t = 0.f;
#pragma unroll
        for (int i = 0; i < CAPS; i++) t += xv[i];

        // p[i] = x[b,i,j] * t[j]  (per-thread partial of score[i])
        float p[CAPS];
#pragma unroll
        for (int i = 0; i < CAPS; i++) p[i] = xv[i] * t;

        // Warp transpose-reduce: 31 SHFLs; lane l ends with this warp's
        // 32-feature partial of score[l].
#pragma unroll
        for (int d = 16; d >= 1; d >>= 1) {
            const bool up = (lane & d) != 0;
#pragma unroll
            for (int k = 0; k < d; k++) {
                float send = up ? p[k] : p[k + d];
                float recv = __shfl_xor_sync(0xffffffffu, send, d);
                p[k] = (up ? p[k + d] : p[k]) + recv;
            }
        }
        warp_part[wid][lane] = p[0];
        __syncthreads();

        // All warps redundantly compute the 32-wide softmax (no 2nd barrier,
        // no single-warp serialization).
        float s = 0.f;
#pragma unroll
        for (int w = 0; w < 8; w++) s += warp_part[w][lane];
        s *= (1.0f / 16.0f);                // 1/sqrt(FEAT)

        float m = s;
#pragma unroll
        for (int d = 16; d >= 1; d >>= 1)
            m = fmaxf(m, __shfl_xor_sync(0xffffffffu, m, d));
        float e = __expf(s - m);
        float sum = e;
#pragma unroll
        for (int d = 16; d >= 1; d >>= 1)
            sum += __shfl_xor_sync(0xffffffffu, sum, d);
        const float attn_lane = e / sum;    // attn for capsule `lane`

        // out[b,j] = sum_i x[b,i,j] * (attn[i] + bias[i,j])
        float acc = 0.f;
#pragma unroll
        for (int i = 0; i < CAPS; i++) {
            const float ai = __shfl_sync(0xffffffffu, attn_lane, i);
            acc = fmaf(xv[i], ai + breg[i], acc);
        }
        out[(size_t)b * FEAT + tid] = acc;
    }
}

extern "C" void kernel_launch(void* const* d_in, const int* in_sizes, int n_in,
                              void* d_out, int out_size)
{
    const float* x    = (const float*)d_in[0];   // inputs [B, 32, 256] fp32
    const float* bias = (const float*)d_in[1];   // bias   [32, 256]   fp32
    float* out        = (float*)d_out;           // out    [B, 256]    fp32

    const int B = in_sizes[0] / (CAPS * FEAT);

    cudaFuncSetAttribute(router_kernel,
                         cudaFuncAttributeMaxDynamicSharedMemorySize,
                         SMEM_BYTES);

    int grid = 304;                    // 2 persistent CTAs per SM (152 SMs)
    if (grid > B) grid = B;
    router_kernel<<<grid, 256, SMEM_BYTES>>>(x, bias, out, B);
}